// round 16
// baseline (speedup 1.0000x reference)
#include <cuda_runtime.h>
#include <cuda_bf16.h>
#include <math.h>

// H = [[1.2, c],[c, 0.01]], c = cos(theta)
// inv = 1/(1.2*0.01 - c^2) * [[0.01, -c],[-c, 1.2]]
//
// FINAL (converged): structure = R13, the measured optimum at 29.6us bench /
// 25.8us ncu. 160MB irreducible traffic; profile fingerprint DRAM 53% /
// L2 46% / issue 28% = latency-bound streaming at the write-dominated floor.
//
// Numerics (verified, rel_err 1.92e-5): bulk = __cosf + rcp.approx;
// near-singular elements (|det| < 1e-5, ~0.005%) redo with correctly-rounded
// fp32 cos (via fp64) + correctly-rounded divide — they own the ref L2 norm.
//
// Search record (all axes probed both directions):
//   R7:  1 elem/thread (MLP=1)                       35.3us
//   R8:  4 elem/thread, front-batched scalar LDGs,
//        per-element paced STG.128                   29.9us
//   R9:  8 elem/thread (L1tex queue overflow)        31.5us
//   R10: persistent grid + double buffering          33.2us
//   R11: batched compute + ballot-gated repair       31.2us (store burst)
//   R12: R8 re-run                                   30.8us (noise band)
//   R13: R8 + __ldcs read-once input                 29.6us  << BEST
//   R14: 512-thread CTAs (spread-law probe)          30.8us (neutral)
// Load-bearing properties: per-warp MLP=4 front-batched coalesced loads;
// one STG.128 (512B/warp, 4 lines) paced between MUFU chains; default store
// policy; rare repair predicated per element (no ballot, no batching).

__device__ __forceinline__ float rcp_approx(float x) {
    float r;
    asm("rcp.approx.f32 %0, %1;" : "=f"(r) : "f"(x));
    return r;
}

__device__ __forceinline__ float4 invert_one(float t)
{
    const float ad = 1.2f * 0.01f;

    float c   = __cosf(t);
    float det = __fsub_rn(ad, __fmul_rn(c, c));
    float r   = rcp_approx(det);

    if (fabsf(det) < 1e-5f) {                 // ~0.005% of elements
        c   = (float)cos((double)t);
        det = __fsub_rn(ad, __fmul_rn(c, c));
        r   = __fdiv_rn(1.0f, det);
    }

    float4 v;
    v.x = __fmul_rn(0.01f, r);
    v.y = __fmul_rn(-c,    r);
    v.z = v.y;
    v.w = __fmul_rn(1.2f,  r);
    return v;
}

__global__ __launch_bounds__(256) void inv2x2_kernel_v15(
    const float* __restrict__ theta,
    float4* __restrict__ out,
    int n)
{
    const int T = 256;                         // blockDim.x
    int base = blockIdx.x * (T * 4) + threadIdx.x;

    if (base + 3 * T < n) {
        // Front-batched independent loads: 4 LDGs in flight per warp before
        // any compute (MLP_p1 = 4), each a coalesced 128B warp load.
        // Evict-first: input is read exactly once.
        float t0 = __ldcs(&theta[base]);
        float t1 = __ldcs(&theta[base +     T]);
        float t2 = __ldcs(&theta[base + 2 * T]);
        float t3 = __ldcs(&theta[base + 3 * T]);

        // Compute + store interleaved; each store is a coalesced 512B/warp
        // STG.128 spaced between MUFU chains (store pacing is load-bearing).
        out[base]         = invert_one(t0);
        out[base +     T] = invert_one(t1);
        out[base + 2 * T] = invert_one(t2);
        out[base + 3 * T] = invert_one(t3);
    } else {
        // Tail (unused for n = 8388608, divisible by 1024).
        for (int k = 0; k < 4; k++) {
            int i = base + k * T;
            if (i < n) out[i] = invert_one(__ldcs(&theta[i]));
        }
    }
}

extern "C" void kernel_launch(void* const* d_in, const int* in_sizes, int n_in,
                              void* d_out, int out_size) {
    const float* theta = (const float*)d_in[0];
    float4* out = (float4*)d_out;
    int n = in_sizes[0];                       // 8388608

    const int threads = 256;
    int elems_per_block = threads * 4;         // 1024
    int blocks = (n + elems_per_block - 1) / elems_per_block;   // 8192
    inv2x2_kernel_v15<<<blocks, threads>>>(theta, out, n);
}

// round 17
// speedup vs baseline: 1.0031x; 1.0031x over previous
#include <cuda_runtime.h>
#include <cuda_bf16.h>
#include <math.h>

// H = [[1.2, c],[c, 0.01]], c = cos(theta)
// inv = 1/(1.2*0.01 - c^2) * [[0.01, -c],[-c, 1.2]]
//
// Numerics (verified, rel_err 1.92e-5): bulk = __cosf + rcp.approx;
// near-singular elements (|det| < 1e-5, ~0.005%) repaired with correctly-
// rounded fp32 cos (via fp64) + correctly-rounded divide, then RE-STORED.
//
// R16 vs R13 (29.6us best): remove the 4 per-element BSSY/BSYNC branch
// envelopes (~35cyc each, paid even untaken) from the hot path. R11 proved
// the branches were doubling as store-pacing barriers, so pacing is now
// enforced explicitly with asm memory clobbers between element stores.
// One combined rare-repair branch (single BSSY) after the stores re-stores
// corrected values for the ~400 chip-wide rare elements.
//
// History: R7 35.3 | R8 29.9 | R9(MLP8) 31.5 | R10(persist) 33.2 |
//   R11(store burst) 31.2 | R12(=R8) 30.8 | R13(+ldcs) 29.6 BEST |
//   R14(512thr) 30.8 | R15(=R13) 30.8
// Load-bearing: MLP=4 front-batched coalesced loads; one paced STG.128
// (512B/warp) per element; default store policy.

__device__ __forceinline__ float rcp_approx(float x) {
    float r;
    asm("rcp.approx.f32 %0, %1;" : "=f"(r) : "f"(x));
    return r;
}

__device__ __forceinline__ float4 pack_inv(float c, float r)
{
    float4 v;
    v.x = __fmul_rn(0.01f, r);
    v.y = __fmul_rn(-c,    r);
    v.z = v.y;
    v.w = __fmul_rn(1.2f,  r);
    return v;
}

// Exact repair: correctly-rounded fp32 cos via fp64, reference op-order det,
// correctly-rounded divide. Cold path, keep out of hot-path regalloc.
__device__ __noinline__ float4 invert_exact(float t)
{
    const float ad = 1.2f * 0.01f;
    float c   = (float)cos((double)t);
    float det = __fsub_rn(ad, __fmul_rn(c, c));
    float r   = __fdiv_rn(1.0f, det);
    return pack_inv(c, r);
}

// Fast per-element: branch-free.
__device__ __forceinline__ float4 invert_fast(float t, float& det_out)
{
    const float ad = 1.2f * 0.01f;
    float c   = __cosf(t);
    float det = __fsub_rn(ad, __fmul_rn(c, c));
    det_out   = det;
    return pack_inv(c, rcp_approx(det));
}

__global__ __launch_bounds__(256) void inv2x2_kernel_v16(
    const float* __restrict__ theta,
    float4* __restrict__ out,
    int n)
{
    const int T = 256;                         // blockDim.x
    const float thresh = 1e-5f;
    int base = blockIdx.x * (T * 4) + threadIdx.x;

    if (base + 3 * T < n) {
        // Front-batched independent loads (MLP_p1 = 4), coalesced 128B/warp,
        // evict-first (input read exactly once).
        float t0 = __ldcs(&theta[base]);
        float t1 = __ldcs(&theta[base +     T]);
        float t2 = __ldcs(&theta[base + 2 * T]);
        float t3 = __ldcs(&theta[base + 3 * T]);

        float d0, d1, d2, d3;

        // Branch-free compute + paced stores. The empty asm with a memory
        // clobber pins each store in place so ptxas cannot sink them into a
        // terminal burst (the R11 pathology); MUFU/FMA work still schedules
        // freely across the barriers.
        out[base]         = invert_fast(t0, d0);
        asm volatile("" ::: "memory");
        out[base +     T] = invert_fast(t1, d1);
        asm volatile("" ::: "memory");
        out[base + 2 * T] = invert_fast(t2, d2);
        asm volatile("" ::: "memory");
        out[base + 3 * T] = invert_fast(t3, d3);

        // Single rare-repair envelope (one BSSY instead of four). True for
        // ~0.005% of elements chip-wide; re-store the exact result.
        bool n0 = fabsf(d0) < thresh, n1 = fabsf(d1) < thresh;
        bool n2 = fabsf(d2) < thresh, n3 = fabsf(d3) < thresh;
        if (n0 | n1 | n2 | n3) {
            if (n0) out[base]         = invert_exact(t0);
            if (n1) out[base +     T] = invert_exact(t1);
            if (n2) out[base + 2 * T] = invert_exact(t2);
            if (n3) out[base + 3 * T] = invert_exact(t3);
        }
    } else {
        // Tail (unused for n = 8388608, divisible by 1024).
        for (int k = 0; k < 4; k++) {
            int i = base + k * T;
            if (i < n) {
                float t = __ldcs(&theta[i]);
                float d;
                float4 v = invert_fast(t, d);
                if (fabsf(d) < thresh) v = invert_exact(t);
                out[i] = v;
            }
        }
    }
}

extern "C" void kernel_launch(void* const* d_in, const int* in_sizes, int n_in,
                              void* d_out, int out_size) {
    const float* theta = (const float*)d_in[0];
    float4* out = (float4*)d_out;
    int n = in_sizes[0];                       // 8388608

    const int threads = 256;
    int elems_per_block = threads * 4;         // 1024
    int blocks = (n + elems_per_block - 1) / elems_per_block;   // 8192
    inv2x2_kernel_v16<<<blocks, threads>>>(theta, out, n);
}